// round 14
// baseline (speedup 1.0000x reference)
#include <cuda_runtime.h>
#include <cuda_fp16.h>
#include <math.h>
#include <stdint.h>

// Problem constants
#define Bq   4
#define Tq   2048
#define Cq   1024
#define Hq   16
#define Dq   64
#define NTOK (Bq * Tq)        // 8192
#define C3   (3 * Cq)         // 3072

// ---------------------------------------------------------------------------
// Scratch (allocation-free rule: __device__ globals)
// ---------------------------------------------------------------------------
__device__ __half g_qkvh[(size_t)NTOK * C3];
__device__ __half g_qkvl[(size_t)NTOK * C3];
__device__ __half g_xh[(size_t)NTOK * Cq];
__device__ __half g_xl[(size_t)NTOK * Cq];
__device__ __half g_wah[(size_t)C3 * Cq];     // w_attn single fp16
__device__ __half g_yh[(size_t)NTOK * Cq];
__device__ __half g_yl[(size_t)NTOK * Cq];
__device__ __half g_wph[(size_t)Cq * Cq];     // w_proj single fp16

// ---------------------------------------------------------------------------
// Portable PTX helpers (sm_80+: cp.async, ldmatrix, mma.sync)
// ---------------------------------------------------------------------------
__device__ __forceinline__ uint32_t s2u(const void* p) {
    uint32_t a;
    asm("{ .reg .u64 t; cvta.to.shared.u64 t, %1; cvt.u32.u64 %0, t; }"
        : "=r"(a) : "l"(p));
    return a;
}
__device__ __forceinline__ void cp16(uint32_t s, const void* g) {
    asm volatile("cp.async.cg.shared.global [%0], [%1], 16;"
                 :: "r"(s), "l"(g) : "memory");
}
#define CP_COMMIT() asm volatile("cp.async.commit_group;" ::: "memory")
#define CP_WAIT0()  asm volatile("cp.async.wait_group 0;" ::: "memory")
#define CP_WAIT1()  asm volatile("cp.async.wait_group 1;" ::: "memory")

__device__ __forceinline__ void ldsm4(uint32_t* r, uint32_t a) {
    asm volatile("ldmatrix.sync.aligned.m8n8.x4.shared.b16 {%0,%1,%2,%3}, [%4];"
                 : "=r"(r[0]), "=r"(r[1]), "=r"(r[2]), "=r"(r[3]) : "r"(a));
}
__device__ __forceinline__ void ldsm4t(uint32_t* r, uint32_t a) {
    asm volatile("ldmatrix.sync.aligned.m8n8.x4.trans.shared.b16 {%0,%1,%2,%3}, [%4];"
                 : "=r"(r[0]), "=r"(r[1]), "=r"(r[2]), "=r"(r[3]) : "r"(a));
}
__device__ __forceinline__ void mma16816(float* c, const uint32_t* a,
                                         const uint32_t* b) {
    asm volatile("mma.sync.aligned.m16n8k16.row.col.f32.f16.f16.f32 "
                 "{%0,%1,%2,%3}, {%4,%5,%6,%7}, {%8,%9}, {%0,%1,%2,%3};"
                 : "+f"(c[0]), "+f"(c[1]), "+f"(c[2]), "+f"(c[3])
                 : "r"(a[0]), "r"(a[1]), "r"(a[2]), "r"(a[3]),
                   "r"(b[0]), "r"(b[1]));
}
// fp32 pair -> packed fp16 hi + packed fp16 residual (captures ~22 bits)
__device__ __forceinline__ void split2(float v0, float v1,
                                       uint32_t& h, uint32_t& l) {
    __half2 hh = __floats2half2_rn(v0, v1);
    float r0 = v0 - __low2float(hh);
    float r1 = v1 - __high2float(hh);
    __half2 ll = __floats2half2_rn(r0, r1);
    h = *(uint32_t*)&hh;
    l = *(uint32_t*)&ll;
}

// ---------------------------------------------------------------------------
// fp32 -> (fp16 hi, fp16 lo) split (input x)
// ---------------------------------------------------------------------------
__global__ void split_kernel(const float* __restrict__ src,
                             __half* __restrict__ hi,
                             __half* __restrict__ lo, int n)
{
    int i = (blockIdx.x * blockDim.x + threadIdx.x) * 4;
    if (i >= n) return;
    float4 v = *(const float4*)(src + i);
    uint32_t h0, l0, h1, l1;
    split2(v.x, v.y, h0, l0);
    split2(v.z, v.w, h1, l1);
    *(uint2*)(hi + i) = make_uint2(h0, h1);
    *(uint2*)(lo + i) = make_uint2(l0, l1);
}

// fp32 -> single fp16 RN (weights)
__global__ void cvt_kernel(const float* __restrict__ src,
                           __half* __restrict__ dst, int n)
{
    int i = (blockIdx.x * blockDim.x + threadIdx.x) * 4;
    if (i >= n) return;
    float4 v = *(const float4*)(src + i);
    __half2 h0 = __floats2half2_rn(v.x, v.y);
    __half2 h1 = __floats2half2_rn(v.z, v.w);
    *(uint2*)(dst + i) = make_uint2(*(uint32_t*)&h0, *(uint32_t*)&h1);
}

// ---------------------------------------------------------------------------
// fp16 2-term HMMA GEMM: C = (Ah+Al) @ Bh^T + bias, fp32 acc.
// 128x128x32 tile, 3-stage cp.async, 8 warps (4m x 2n), 2 CTAs/SM.
// NEW: B-fragment ping-pong preload (distance 1) to hide LDS latency.
// SPLIT=1: write fp16 hi/lo pair arrays instead of fp32.
// ---------------------------------------------------------------------------
#define BM 128
#define BN 128
#define BK 32
#define MAT_B   (BM * 64)            // 8192 bytes per matrix tile
#define STAGE_B (3 * MAT_B)          // 24576 (Ah, Al, Bh)
#define GEMM_SMEM (3 * STAGE_B)      // 73728

template<int SPLIT>
__global__ __launch_bounds__(256, 2)
void gemm_hmma(const __half* __restrict__ Ah, const __half* __restrict__ Al,
               const __half* __restrict__ Bh,
               const float* __restrict__ bias, float* __restrict__ C,
               __half* __restrict__ Ch, __half* __restrict__ Cl,
               int M, int N, int K)
{
    extern __shared__ __align__(1024) char smem[];
    const uint32_t sbase = s2u(smem);
    const int tid  = threadIdx.x;
    const int wid  = tid >> 5;
    const int lane = tid & 31;
    const int m0 = blockIdx.y * BM;
    const int n0 = blockIdx.x * BN;
    const int NC = K / BK;

    const int wm = (wid >> 1) * 32;
    const int wn = (wid & 1) * 64;

    const int lrow = tid >> 1;
    const int lcs  = (tid & 1) * 2;
    const uint32_t so0 = lrow * 64 + ((lcs ^ (lrow & 3)) << 4);
    const uint32_t so1 = lrow * 64 + (((lcs + 1) ^ (lrow & 3)) << 4);

    const __half* gAh = Ah + (size_t)(m0 + lrow) * K + lcs * 8;
    const __half* gAl = Al + (size_t)(m0 + lrow) * K + lcs * 8;
    const __half* gBh = Bh + (size_t)(n0 + lrow) * K + lcs * 8;

    auto load_stage = [&](int st, int c) {
        const uint32_t sb = sbase + st * STAGE_B;
        const int off = c * BK;
        cp16(sb + so0,           gAh + off);
        cp16(sb + so1,           gAh + off + 8);
        cp16(sb + MAT_B + so0,   gAl + off);
        cp16(sb + MAT_B + so1,   gAl + off + 8);
        cp16(sb + 2*MAT_B + so0, gBh + off);
        cp16(sb + 2*MAT_B + so1, gBh + off + 8);
    };

    float acc[2][8][4];
#pragma unroll
    for (int i = 0; i < 2; i++)
#pragma unroll
        for (int j = 0; j < 8; j++)
#pragma unroll
            for (int k = 0; k < 4; k++) acc[i][j][k] = 0.f;

    const int g   = lane >> 3;
    const int l7  = lane & 7;
    const int arow = wm + (g & 1) * 8 + l7;
    const int achk = g >> 1;
    const int brow = wn + ((g & 2) << 2) + l7;
    const int bchk = g & 1;

    load_stage(0, 0); CP_COMMIT();
    load_stage(1, 1); CP_COMMIT();

    for (int c = 0; c < NC; c++) {
        const int st = c % 3;
        CP_WAIT1();
        __syncthreads();

        if (c + 2 < NC) load_stage((c + 2) % 3, c + 2);
        CP_COMMIT();

        const uint32_t sb  = sbase + st * STAGE_B;
        const uint32_t sAh = sb;
        const uint32_t sAl = sb + MAT_B;
        const uint32_t sBh = sb + 2 * MAT_B;

#pragma unroll
        for (int s = 0; s < 2; s++) {
            uint32_t ah[2][4], al[2][4];
#pragma unroll
            for (int mt = 0; mt < 2; mt++) {
                const int r = arow + mt * 16;
                const int ck = achk + 2 * s;
                const uint32_t ad = r * 64 + ((ck ^ (r & 3)) << 4);
                ldsm4(ah[mt], sAh + ad);
                ldsm4(al[mt], sAl + ad);
            }
            // B-fragment ping-pong: preload ng+1 while computing ng
            uint32_t bbuf[2][4];
            {
                const int r = brow;
                const int ck = bchk + 2 * s;
                ldsm4(bbuf[0], sBh + r * 64 + ((ck ^ (r & 3)) << 4));
            }
#pragma unroll
            for (int ng = 0; ng < 4; ng++) {
                if (ng < 3) {
                    const int r = brow + (ng + 1) * 16;
                    const int ck = bchk + 2 * s;
                    ldsm4(bbuf[(ng + 1) & 1], sBh + r * 64 + ((ck ^ (r & 3)) << 4));
                }
                const uint32_t* bh = bbuf[ng & 1];
#pragma unroll
                for (int mt = 0; mt < 2; mt++) {
                    mma16816(acc[mt][2*ng],   ah[mt], bh);
                    mma16816(acc[mt][2*ng+1], ah[mt], bh + 2);
                    mma16816(acc[mt][2*ng],   al[mt], bh);
                    mma16816(acc[mt][2*ng+1], al[mt], bh + 2);
                }
            }
        }
        __syncthreads();
    }

    const int r = lane >> 2;
    const int t = lane & 3;
#pragma unroll
    for (int nt = 0; nt < 8; nt++) {
        const int col = n0 + wn + nt * 8 + t * 2;
        const float2 bv = *(const float2*)(bias + col);
#pragma unroll
        for (int mt = 0; mt < 2; mt++) {
            const int row0 = m0 + wm + mt * 16 + r;
            float v0 = acc[mt][nt][0] + bv.x, v1 = acc[mt][nt][1] + bv.y;
            float v2 = acc[mt][nt][2] + bv.x, v3 = acc[mt][nt][3] + bv.y;
            if (SPLIT) {
                uint32_t h01, l01, h23, l23;
                split2(v0, v1, h01, l01);
                split2(v2, v3, h23, l23);
                *(uint32_t*)(Ch + (size_t)row0 * N + col)       = h01;
                *(uint32_t*)(Cl + (size_t)row0 * N + col)       = l01;
                *(uint32_t*)(Ch + (size_t)(row0 + 8) * N + col) = h23;
                *(uint32_t*)(Cl + (size_t)(row0 + 8) * N + col) = l23;
            } else {
                *(float2*)(C + (size_t)row0 * N + col)       = make_float2(v0, v1);
                *(float2*)(C + (size_t)(row0 + 8) * N + col) = make_float2(v2, v3);
            }
        }
    }
}

// ---------------------------------------------------------------------------
// Tensorized flash attention (causal), fp32 softmax.
// 2-term: S = (Qh+Ql)Kh, O = (Ph+Pl)Vh; K/V single fp16.
// NEW: distance-2 ping-pong preload of K and V fragments (flattened 16-iter
// loops) to cover the ~29cyc LDS latency with ~2 iterations of MMA work.
// BQ=128, BKV=64, 8 warps, double-buffered K/V tiles, 1 CTA/SM.
// ---------------------------------------------------------------------------
#define FQ_B   16384                 // Q tile hi or lo: 128 rows x 128 B
#define FKV_B  8192                  // one K or V tile: 64 rows x 128 B
#define FSTG_B (2 * FKV_B)           // Kh, Vh
#define FLASH_SMEM (2 * FQ_B + 2 * FSTG_B)   // 65536

__global__ __launch_bounds__(256, 1)
void flash_hmma(const __half* __restrict__ qkvh,
                const __half* __restrict__ qkvl,
                __half* __restrict__ yh,
                __half* __restrict__ yl)
{
    extern __shared__ __align__(1024) char smem[];
    const uint32_t sbase = s2u(smem);
    const uint32_t sQh = sbase;
    const uint32_t sQl = sbase + FQ_B;

    const int tid  = threadIdx.x;
    const int wq   = tid >> 5;            // warp: q rows wq*16..+15
    const int lane = tid & 31;
    const int qt   = gridDim.x - 1 - blockIdx.x;   // heavy CTAs first
    const int bh   = blockIdx.y;
    const int b    = bh >> 4;
    const int h    = bh & 15;
    const int q0   = qt * 128;
    const int jtmax = 2 * qt + 1;

    const int g  = lane >> 3;
    const int l7 = lane & 7;
    const int r  = lane >> 2;
    const int t  = lane & 3;

    // ---- load Q tile (hi+lo) ----
    {
        const int row = tid >> 1;
        const int cb  = (tid & 1) * 4;
        const size_t gb = (size_t)(b * Tq + q0 + row) * C3 + h * Dq;
#pragma unroll
        for (int u = 0; u < 4; u++) {
            const int c = cb + u;
            const uint32_t off = row * 128 + ((c ^ (row & 7)) << 4);
            cp16(sQh + off, qkvh + gb + c * 8);
            cp16(sQl + off, qkvl + gb + c * 8);
        }
    }
    // ---- load K/V tile (hi only) into stage s ----
    auto load_kv = [&](int jt, int s) {
        const uint32_t st = sbase + 2 * FQ_B + s * FSTG_B;
#pragma unroll
        for (int u = 0; u < 2; u++) {
            const int idx = tid * 2 + u;
            const int row = idx >> 3;
            const int c   = idx & 7;
            const uint32_t off = row * 128 + ((c ^ (row & 7)) << 4);
            const size_t gk = (size_t)(b * Tq + jt * 64 + row) * C3 + Cq + h * Dq + c * 8;
            const size_t gv = gk + Cq;
            cp16(st + off,           qkvh + gk);
            cp16(st + FKV_B + off,   qkvh + gv);
        }
    };
    load_kv(0, 0);
    CP_COMMIT();
    CP_WAIT0();
    __syncthreads();

    // ---- Q fragments (registers, 4 k-chunks x 4 regs, hi+lo) ----
    uint32_t qhf[4][4], qlf[4][4];
    {
        const int arow = wq * 16 + (g & 1) * 8 + l7;
#pragma unroll
        for (int kc = 0; kc < 4; kc++) {
            const int ck = 2 * kc + (g >> 1);
            const uint32_t ad = arow * 128 + ((ck ^ (arow & 7)) << 4);
            ldsm4(qhf[kc], sQh + ad);
            ldsm4(qlf[kc], sQl + ad);
        }
    }

    float oacc[8][4];
#pragma unroll
    for (int i = 0; i < 8; i++)
#pragma unroll
        for (int j = 0; j < 4; j++) oacc[i][j] = 0.f;
    float m0r = -1e30f, m1r = -1e30f, l0r = 0.f, l1r = 0.f;

    const int qr0 = q0 + wq * 16 + r;   // this lane's first q row
    const int kmax_w = q0 + wq * 16 + 15;

    for (int jt = 0; jt <= jtmax; jt++) {
        const int s = jt & 1;
        const int k0 = jt * 64;
        if (jt > 0) CP_WAIT0();
        __syncthreads();
        if (jt < jtmax) { load_kv(jt + 1, s ^ 1); CP_COMMIT(); }

        if (k0 <= kmax_w) {
            const uint32_t st  = sbase + 2 * FQ_B + s * FSTG_B;
            const uint32_t sKh = st;
            const uint32_t sVh = st + FKV_B;

            // ---- S = (Qh+Ql) Kh^T (fp32 acc) ----
            // flattened idx = ntp*4 + kc; distance-2 fragment pipeline
            float sacc[8][4];
#pragma unroll
            for (int i = 0; i < 8; i++)
#pragma unroll
                for (int j = 0; j < 4; j++) sacc[i][j] = 0.f;

            auto kaddr = [&](int idx) {
                const int ntp = idx >> 2, kc = idx & 3;
                const int krow = ntp * 16 + ((g & 2) << 2) + l7;
                const int ck = 2 * kc + (g & 1);
                return sKh + krow * 128 + ((ck ^ (krow & 7)) << 4);
            };
            uint32_t kbuf[2][4];
            ldsm4(kbuf[0], kaddr(0));
            ldsm4(kbuf[1], kaddr(1));
#pragma unroll
            for (int idx = 0; idx < 16; idx++) {
                const int ntp = idx >> 2, kc = idx & 3;
                const uint32_t* kh = kbuf[idx & 1];
                mma16816(sacc[2*ntp],   qhf[kc], kh);
                mma16816(sacc[2*ntp+1], qhf[kc], kh + 2);
                mma16816(sacc[2*ntp],   qlf[kc], kh);
                mma16816(sacc[2*ntp+1], qlf[kc], kh + 2);
                if (idx < 14) ldsm4(kbuf[idx & 1], kaddr(idx + 2));
            }

            // ---- scale + causal mask ----
            const bool need_mask = (k0 + 63 > q0 + wq * 16);
#pragma unroll
            for (int nt = 0; nt < 8; nt++) {
#pragma unroll
                for (int j = 0; j < 4; j++) sacc[nt][j] *= 0.125f;
                if (need_mask) {
                    const int col = k0 + nt * 8 + 2 * t;
                    if (col     > qr0)     sacc[nt][0] = -1e30f;
                    if (col + 1 > qr0)     sacc[nt][1] = -1e30f;
                    if (col     > qr0 + 8) sacc[nt][2] = -1e30f;
                    if (col + 1 > qr0 + 8) sacc[nt][3] = -1e30f;
                }
            }

            // ---- online softmax ----
            float mx0 = -1e30f, mx1 = -1e30f;
#pragma unroll
            for (int nt = 0; nt < 8; nt++) {
                mx0 = fmaxf(mx0, fmaxf(sacc[nt][0], sacc[nt][1]));
                mx1 = fmaxf(mx1, fmaxf(sacc[nt][2], sacc[nt][3]));
            }
            mx0 = fmaxf(mx0, __shfl_xor_sync(0xffffffffu, mx0, 1));
            mx0 = fmaxf(mx0, __shfl_xor_sync(0xffffffffu, mx0, 2));
            mx1 = fmaxf(mx1, __shfl_xor_sync(0xffffffffu, mx1, 1));
            mx1 = fmaxf(mx1, __shfl_xor_sync(0xffffffffu, mx1, 2));
            const float mn0 = fmaxf(m0r, mx0);
            const float mn1 = fmaxf(m1r, mx1);
            const float al0 = __expf(m0r - mn0);
            const float al1 = __expf(m1r - mn1);
            m0r = mn0; m1r = mn1;

            float rs0 = 0.f, rs1 = 0.f;
#pragma unroll
            for (int nt = 0; nt < 8; nt++) {
                sacc[nt][0] = __expf(sacc[nt][0] - mn0);
                sacc[nt][1] = __expf(sacc[nt][1] - mn0);
                sacc[nt][2] = __expf(sacc[nt][2] - mn1);
                sacc[nt][3] = __expf(sacc[nt][3] - mn1);
                rs0 += sacc[nt][0] + sacc[nt][1];
                rs1 += sacc[nt][2] + sacc[nt][3];
            }
            rs0 += __shfl_xor_sync(0xffffffffu, rs0, 1);
            rs0 += __shfl_xor_sync(0xffffffffu, rs0, 2);
            rs1 += __shfl_xor_sync(0xffffffffu, rs1, 1);
            rs1 += __shfl_xor_sync(0xffffffffu, rs1, 2);
            l0r = l0r * al0 + rs0;
            l1r = l1r * al1 + rs1;
#pragma unroll
            for (int nt = 0; nt < 8; nt++) {
                oacc[nt][0] *= al0; oacc[nt][1] *= al0;
                oacc[nt][2] *= al1; oacc[nt][3] *= al1;
            }

            // ---- P fragments (split fp16, A-fragment layout) ----
            uint32_t ph[4][4], pl[4][4];
#pragma unroll
            for (int kc = 0; kc < 4; kc++) {
                split2(sacc[2*kc][0],   sacc[2*kc][1],   ph[kc][0], pl[kc][0]);
                split2(sacc[2*kc][2],   sacc[2*kc][3],   ph[kc][1], pl[kc][1]);
                split2(sacc[2*kc+1][0], sacc[2*kc+1][1], ph[kc][2], pl[kc][2]);
                split2(sacc[2*kc+1][2], sacc[2*kc+1][3], ph[kc][3], pl[kc][3]);
            }

            // ---- O += (Ph+Pl) Vh, distance-2 fragment pipeline ----
            auto vaddr = [&](int idx) {
                const int ntp = idx >> 2, kc = idx & 3;
                const int vrow = kc * 16 + ((g & 1) << 3) + l7;
                const int vc   = 2 * ntp + (g >> 1);
                return sVh + vrow * 128 + ((vc ^ (vrow & 7)) << 4);
            };
            uint32_t vbuf[2][4];
            ldsm4t(vbuf[0], vaddr(0));
            ldsm4t(vbuf[1], vaddr(1));
#pragma unroll
            for (int idx = 0; idx < 16; idx++) {
                const int ntp = idx >> 2, kc = idx & 3;
                const uint32_t* vh = vbuf[idx & 1];
                mma16816(oacc[2*ntp],   ph[kc], vh);
                mma16816(oacc[2*ntp+1], ph[kc], vh + 2);
                mma16816(oacc[2*ntp],   pl[kc], vh);
                mma16816(oacc[2*ntp+1], pl[kc], vh + 2);
                if (idx < 14) ldsm4t(vbuf[idx & 1], vaddr(idx + 2));
            }
        }
    }

    // ---- epilogue: normalize, split-write y ----
    const float inv0 = 1.f / l0r;
    const float inv1 = 1.f / l1r;
    const size_t tok0 = (size_t)(b * Tq + q0 + wq * 16 + r);
    const size_t tok1 = tok0 + 8;
#pragma unroll
    for (int nt = 0; nt < 8; nt++) {
        const int col = h * Dq + nt * 8 + 2 * t;
        uint32_t h01, l01, h23, l23;
        split2(oacc[nt][0] * inv0, oacc[nt][1] * inv0, h01, l01);
        split2(oacc[nt][2] * inv1, oacc[nt][3] * inv1, h23, l23);
        *(uint32_t*)(yh + tok0 * Cq + col) = h01;
        *(uint32_t*)(yl + tok0 * Cq + col) = l01;
        *(uint32_t*)(yh + tok1 * Cq + col) = h23;
        *(uint32_t*)(yl + tok1 * Cq + col) = l23;
    }
}

// ---------------------------------------------------------------------------
extern "C" void kernel_launch(void* const* d_in, const int* in_sizes, int n_in,
                              void* d_out, int out_size)
{
    const float* x      = (const float*)d_in[0];
    const float* w_attn = (const float*)d_in[1];
    const float* b_attn = (const float*)d_in[2];
    const float* w_proj = (const float*)d_in[3];
    const float* b_proj = (const float*)d_in[4];
    float* out = (float*)d_out;

    __half *qkvh, *qkvl, *xh, *xl, *wah, *yh, *yl, *wph;
    cudaGetSymbolAddress((void**)&qkvh, g_qkvh);
    cudaGetSymbolAddress((void**)&qkvl, g_qkvl);
    cudaGetSymbolAddress((void**)&xh,  g_xh);
    cudaGetSymbolAddress((void**)&xl,  g_xl);
    cudaGetSymbolAddress((void**)&wah, g_wah);
    cudaGetSymbolAddress((void**)&yh,  g_yh);
    cudaGetSymbolAddress((void**)&yl,  g_yl);
    cudaGetSymbolAddress((void**)&wph, g_wph);

    cudaFuncSetAttribute(gemm_hmma<0>,
                         cudaFuncAttributeMaxDynamicSharedMemorySize, GEMM_SMEM);
    cudaFuncSetAttribute(gemm_hmma<1>,
                         cudaFuncAttributeMaxDynamicSharedMemorySize, GEMM_SMEM);
    cudaFuncSetAttribute(flash_hmma,
                         cudaFuncAttributeMaxDynamicSharedMemorySize, FLASH_SMEM);

    // x -> fp16 split; weights -> single fp16 RN
    {
        int n1 = NTOK * Cq;
        split_kernel<<<(n1 / 4 + 255) / 256, 256>>>(x, xh, xl, n1);
        int n2 = C3 * Cq;
        cvt_kernel<<<(n2 / 4 + 255) / 256, 256>>>(w_attn, wah, n2);
        int n3 = Cq * Cq;
        cvt_kernel<<<(n3 / 4 + 255) / 256, 256>>>(w_proj, wph, n3);
    }

    // 1) qkv = x @ w_attn^T + b_attn  -> split fp16 directly
    {
        dim3 grid(C3 / BN, NTOK / BM);
        gemm_hmma<1><<<grid, 256, GEMM_SMEM>>>(xh, xl, wah, b_attn,
                                               nullptr, qkvh, qkvl,
                                               NTOK, C3, Cq);
    }
    // 2) tensorized flash attention -> split y
    {
        dim3 grid(Tq / 128, Bq * Hq);
        flash_hmma<<<grid, 256, FLASH_SMEM>>>(qkvh, qkvl, yh, yl);
    }
    // 3) out = y @ w_proj^T + b_proj  (fp32 out)
    {
        dim3 grid(Cq / BN, NTOK / BM);
        gemm_hmma<0><<<grid, 256, GEMM_SMEM>>>(yh, yl, wph, b_proj,
                                               out, nullptr, nullptr,
                                               NTOK, Cq, Cq);
    }
}

// round 16
// speedup vs baseline: 1.1623x; 1.1623x over previous
#include <cuda_runtime.h>
#include <cuda_fp16.h>
#include <math.h>
#include <stdint.h>

// Problem constants
#define Bq   4
#define Tq   2048
#define Cq   1024
#define Hq   16
#define Dq   64
#define NTOK (Bq * Tq)        // 8192
#define C3   (3 * Cq)         // 3072

// ---------------------------------------------------------------------------
// Scratch (allocation-free rule: __device__ globals)
// ---------------------------------------------------------------------------
__device__ __half g_qkv[(size_t)NTOK * C3];   // single fp16 qkv
__device__ __half g_xh[(size_t)NTOK * Cq];
__device__ __half g_xl[(size_t)NTOK * Cq];
__device__ __half g_wah[(size_t)C3 * Cq];     // w_attn single fp16
__device__ __half g_y[(size_t)NTOK * Cq];     // single fp16 y
__device__ __half g_wph[(size_t)Cq * Cq];     // w_proj single fp16

// ---------------------------------------------------------------------------
// Portable PTX helpers (sm_80+: cp.async, ldmatrix, mma.sync)
// ---------------------------------------------------------------------------
__device__ __forceinline__ uint32_t s2u(const void* p) {
    uint32_t a;
    asm("{ .reg .u64 t; cvta.to.shared.u64 t, %1; cvt.u32.u64 %0, t; }"
        : "=r"(a) : "l"(p));
    return a;
}
__device__ __forceinline__ void cp16(uint32_t s, const void* g) {
    asm volatile("cp.async.cg.shared.global [%0], [%1], 16;"
                 :: "r"(s), "l"(g) : "memory");
}
#define CP_COMMIT() asm volatile("cp.async.commit_group;" ::: "memory")
#define CP_WAIT0()  asm volatile("cp.async.wait_group 0;" ::: "memory")
#define CP_WAIT1()  asm volatile("cp.async.wait_group 1;" ::: "memory")

__device__ __forceinline__ void ldsm4(uint32_t* r, uint32_t a) {
    asm volatile("ldmatrix.sync.aligned.m8n8.x4.shared.b16 {%0,%1,%2,%3}, [%4];"
                 : "=r"(r[0]), "=r"(r[1]), "=r"(r[2]), "=r"(r[3]) : "r"(a));
}
__device__ __forceinline__ void ldsm4t(uint32_t* r, uint32_t a) {
    asm volatile("ldmatrix.sync.aligned.m8n8.x4.trans.shared.b16 {%0,%1,%2,%3}, [%4];"
                 : "=r"(r[0]), "=r"(r[1]), "=r"(r[2]), "=r"(r[3]) : "r"(a));
}
__device__ __forceinline__ void mma16816(float* c, const uint32_t* a,
                                         const uint32_t* b) {
    asm volatile("mma.sync.aligned.m16n8k16.row.col.f32.f16.f16.f32 "
                 "{%0,%1,%2,%3}, {%4,%5,%6,%7}, {%8,%9}, {%0,%1,%2,%3};"
                 : "+f"(c[0]), "+f"(c[1]), "+f"(c[2]), "+f"(c[3])
                 : "r"(a[0]), "r"(a[1]), "r"(a[2]), "r"(a[3]),
                   "r"(b[0]), "r"(b[1]));
}
// fp32 pair -> packed fp16 hi + packed fp16 residual (captures ~22 bits)
__device__ __forceinline__ void split2(float v0, float v1,
                                       uint32_t& h, uint32_t& l) {
    __half2 hh = __floats2half2_rn(v0, v1);
    float r0 = v0 - __low2float(hh);
    float r1 = v1 - __high2float(hh);
    __half2 ll = __floats2half2_rn(r0, r1);
    h = *(uint32_t*)&hh;
    l = *(uint32_t*)&ll;
}
__device__ __forceinline__ uint32_t pack_h2(float v0, float v1) {
    __half2 hh = __floats2half2_rn(v0, v1);
    return *(uint32_t*)&hh;
}

// ---------------------------------------------------------------------------
// fp32 -> (fp16 hi, fp16 lo) split (input x)
// ---------------------------------------------------------------------------
__global__ void split_kernel(const float* __restrict__ src,
                             __half* __restrict__ hi,
                             __half* __restrict__ lo, int n)
{
    int i = (blockIdx.x * blockDim.x + threadIdx.x) * 4;
    if (i >= n) return;
    float4 v = *(const float4*)(src + i);
    uint32_t h0, l0, h1, l1;
    split2(v.x, v.y, h0, l0);
    split2(v.z, v.w, h1, l1);
    *(uint2*)(hi + i) = make_uint2(h0, h1);
    *(uint2*)(lo + i) = make_uint2(l0, l1);
}

// fp32 -> single fp16 RN (weights)
__global__ void cvt_kernel(const float* __restrict__ src,
                           __half* __restrict__ dst, int n)
{
    int i = (blockIdx.x * blockDim.x + threadIdx.x) * 4;
    if (i >= n) return;
    float4 v = *(const float4*)(src + i);
    *(uint2*)(dst + i) = make_uint2(pack_h2(v.x, v.y), pack_h2(v.z, v.w));
}

// ---------------------------------------------------------------------------
// fp16 HMMA GEMM, TERMS-term A x single-B: C = (Ah[+Al]) @ Bh^T + bias.
// TERMS=2: A split (hi+lo).  TERMS=1: A single.
// OUTH=1: write single fp16 output.  OUTH=0: write fp32.
// 128x128x32 tile, 3-stage cp.async, 8 warps (4m x 2n), 2 CTAs/SM.
// ---------------------------------------------------------------------------
#define BM 128
#define BN 128
#define BK 32
#define MAT_B   (BM * 64)            // 8192 bytes per matrix tile

template<int TERMS, int OUTH>
__global__ __launch_bounds__(256, 2)
void gemm_hmma(const __half* __restrict__ Ah, const __half* __restrict__ Al,
               const __half* __restrict__ Bh,
               const float* __restrict__ bias, float* __restrict__ C,
               __half* __restrict__ Ch,
               int M, int N, int K)
{
    constexpr int SB = (TERMS + 1) * MAT_B;   // stage bytes
    extern __shared__ __align__(1024) char smem[];
    const uint32_t sbase = s2u(smem);
    const int tid  = threadIdx.x;
    const int wid  = tid >> 5;
    const int lane = tid & 31;
    const int m0 = blockIdx.y * BM;
    const int n0 = blockIdx.x * BN;
    const int NC = K / BK;

    const int wm = (wid >> 1) * 32;
    const int wn = (wid & 1) * 64;

    const int lrow = tid >> 1;
    const int lcs  = (tid & 1) * 2;
    const uint32_t so0 = lrow * 64 + ((lcs ^ (lrow & 3)) << 4);
    const uint32_t so1 = lrow * 64 + (((lcs + 1) ^ (lrow & 3)) << 4);

    const __half* gAh = Ah + (size_t)(m0 + lrow) * K + lcs * 8;
    const __half* gAl = (TERMS == 2) ? Al + (size_t)(m0 + lrow) * K + lcs * 8 : nullptr;
    const __half* gBh = Bh + (size_t)(n0 + lrow) * K + lcs * 8;

    auto load_stage = [&](int st, int c) {
        const uint32_t sb = sbase + st * SB;
        const int off = c * BK;
        cp16(sb + so0,                 gAh + off);
        cp16(sb + so1,                 gAh + off + 8);
        if (TERMS == 2) {
            cp16(sb + MAT_B + so0,     gAl + off);
            cp16(sb + MAT_B + so1,     gAl + off + 8);
        }
        cp16(sb + TERMS*MAT_B + so0,   gBh + off);
        cp16(sb + TERMS*MAT_B + so1,   gBh + off + 8);
    };

    float acc[2][8][4];
#pragma unroll
    for (int i = 0; i < 2; i++)
#pragma unroll
        for (int j = 0; j < 8; j++)
#pragma unroll
            for (int k = 0; k < 4; k++) acc[i][j][k] = 0.f;

    const int g   = lane >> 3;
    const int l7  = lane & 7;
    const int arow = wm + (g & 1) * 8 + l7;
    const int achk = g >> 1;
    const int brow = wn + ((g & 2) << 2) + l7;
    const int bchk = g & 1;

    load_stage(0, 0); CP_COMMIT();
    load_stage(1, 1); CP_COMMIT();

    for (int c = 0; c < NC; c++) {
        const int st = c % 3;
        CP_WAIT1();
        __syncthreads();

        if (c + 2 < NC) load_stage((c + 2) % 3, c + 2);
        CP_COMMIT();

        const uint32_t sb  = sbase + st * SB;
        const uint32_t sAh = sb;
        const uint32_t sAl = sb + MAT_B;
        const uint32_t sBh = sb + TERMS * MAT_B;

#pragma unroll
        for (int s = 0; s < 2; s++) {
            uint32_t ah[2][4], al[2][4];
#pragma unroll
            for (int mt = 0; mt < 2; mt++) {
                const int r = arow + mt * 16;
                const int ck = achk + 2 * s;
                const uint32_t ad = r * 64 + ((ck ^ (r & 3)) << 4);
                ldsm4(ah[mt], sAh + ad);
                if (TERMS == 2) ldsm4(al[mt], sAl + ad);
            }
#pragma unroll
            for (int ng = 0; ng < 4; ng++) {
                const int r = brow + ng * 16;
                const int ck = bchk + 2 * s;
                const uint32_t bd = r * 64 + ((ck ^ (r & 3)) << 4);
                uint32_t bh[4];
                ldsm4(bh, sBh + bd);
#pragma unroll
                for (int mt = 0; mt < 2; mt++) {
                    mma16816(acc[mt][2*ng],   ah[mt], bh);
                    mma16816(acc[mt][2*ng+1], ah[mt], bh + 2);
                    if (TERMS == 2) {
                        mma16816(acc[mt][2*ng],   al[mt], bh);
                        mma16816(acc[mt][2*ng+1], al[mt], bh + 2);
                    }
                }
            }
        }
        __syncthreads();
    }

    const int r = lane >> 2;
    const int t = lane & 3;
#pragma unroll
    for (int nt = 0; nt < 8; nt++) {
        const int col = n0 + wn + nt * 8 + t * 2;
        const float2 bv = *(const float2*)(bias + col);
#pragma unroll
        for (int mt = 0; mt < 2; mt++) {
            const int row0 = m0 + wm + mt * 16 + r;
            float v0 = acc[mt][nt][0] + bv.x, v1 = acc[mt][nt][1] + bv.y;
            float v2 = acc[mt][nt][2] + bv.x, v3 = acc[mt][nt][3] + bv.y;
            if (OUTH) {
                *(uint32_t*)(Ch + (size_t)row0 * N + col)       = pack_h2(v0, v1);
                *(uint32_t*)(Ch + (size_t)(row0 + 8) * N + col) = pack_h2(v2, v3);
            } else {
                *(float2*)(C + (size_t)row0 * N + col)       = make_float2(v0, v1);
                *(float2*)(C + (size_t)(row0 + 8) * N + col) = make_float2(v2, v3);
            }
        }
    }
}

#define GEMM_SMEM2 (3 * 3 * MAT_B)   // TERMS=2: 73728
#define GEMM_SMEM1 (3 * 2 * MAT_B)   // TERMS=1: 49152

// ---------------------------------------------------------------------------
// Tensorized flash attention (causal), fp32 softmax.
// All of Q, K, V consumed as single fp16: S = Q Kh^T (1-term).
// P kept split fp16 (softmax-sensitive path): O = (Ph+Pl) Vh.
// Writes single-fp16 y. BQ=128, BKV=64, 8 warps, double-buffered K/V tiles.
// ---------------------------------------------------------------------------
#define FQ_B   16384                 // Q tile: 128 rows x 128 B
#define FKV_B  8192                  // one K or V tile: 64 rows x 128 B
#define FSTG_B (2 * FKV_B)           // Kh, Vh
#define FLASH_SMEM (FQ_B + 2 * FSTG_B)   // 49152

__global__ __launch_bounds__(256, 1)
void flash_hmma(const __half* __restrict__ qkv,
                __half* __restrict__ y)
{
    extern __shared__ __align__(1024) char smem[];
    const uint32_t sbase = s2u(smem);
    const uint32_t sQ = sbase;

    const int tid  = threadIdx.x;
    const int wq   = tid >> 5;            // warp: q rows wq*16..+15
    const int lane = tid & 31;
    const int qt   = gridDim.x - 1 - blockIdx.x;   // heavy CTAs first
    const int bh   = blockIdx.y;
    const int b    = bh >> 4;
    const int h    = bh & 15;
    const int q0   = qt * 128;
    const int jtmax = 2 * qt + 1;

    const int g  = lane >> 3;
    const int l7 = lane & 7;
    const int r  = lane >> 2;
    const int t  = lane & 3;

    // ---- load Q tile (single fp16) ----
    {
        const int row = tid >> 1;
        const int cb  = (tid & 1) * 4;
        const size_t gb = (size_t)(b * Tq + q0 + row) * C3 + h * Dq;
#pragma unroll
        for (int u = 0; u < 4; u++) {
            const int c = cb + u;
            const uint32_t off = row * 128 + ((c ^ (row & 7)) << 4);
            cp16(sQ + off, qkv + gb + c * 8);
        }
    }
    // ---- load K/V tile into stage s ----
    auto load_kv = [&](int jt, int s) {
        const uint32_t st = sbase + FQ_B + s * FSTG_B;
#pragma unroll
        for (int u = 0; u < 2; u++) {
            const int idx = tid * 2 + u;
            const int row = idx >> 3;
            const int c   = idx & 7;
            const uint32_t off = row * 128 + ((c ^ (row & 7)) << 4);
            const size_t gk = (size_t)(b * Tq + jt * 64 + row) * C3 + Cq + h * Dq + c * 8;
            const size_t gv = gk + Cq;
            cp16(st + off,           qkv + gk);
            cp16(st + FKV_B + off,   qkv + gv);
        }
    };
    load_kv(0, 0);
    CP_COMMIT();
    CP_WAIT0();
    __syncthreads();

    // ---- Q fragments (registers, 4 k-chunks x 4 regs) ----
    uint32_t qf[4][4];
    {
        const int arow = wq * 16 + (g & 1) * 8 + l7;
#pragma unroll
        for (int kc = 0; kc < 4; kc++) {
            const int ck = 2 * kc + (g >> 1);
            const uint32_t ad = arow * 128 + ((ck ^ (arow & 7)) << 4);
            ldsm4(qf[kc], sQ + ad);
        }
    }

    float oacc[8][4];
#pragma unroll
    for (int i = 0; i < 8; i++)
#pragma unroll
        for (int j = 0; j < 4; j++) oacc[i][j] = 0.f;
    float m0r = -1e30f, m1r = -1e30f, l0r = 0.f, l1r = 0.f;

    const int qr0 = q0 + wq * 16 + r;   // this lane's first q row
    const int kmax_w = q0 + wq * 16 + 15;

    for (int jt = 0; jt <= jtmax; jt++) {
        const int s = jt & 1;
        const int k0 = jt * 64;
        if (jt > 0) CP_WAIT0();
        __syncthreads();
        if (jt < jtmax) { load_kv(jt + 1, s ^ 1); CP_COMMIT(); }

        if (k0 <= kmax_w) {
            const uint32_t st  = sbase + FQ_B + s * FSTG_B;
            const uint32_t sKh = st;
            const uint32_t sVh = st + FKV_B;

            // ---- S = Q Kh^T (fp32 acc, 1-term) ----
            float sacc[8][4];
#pragma unroll
            for (int i = 0; i < 8; i++)
#pragma unroll
                for (int j = 0; j < 4; j++) sacc[i][j] = 0.f;

#pragma unroll
            for (int ntp = 0; ntp < 4; ntp++) {
                const int krow = ntp * 16 + ((g & 2) << 2) + l7;
#pragma unroll
                for (int kc = 0; kc < 4; kc++) {
                    const int ck = 2 * kc + (g & 1);
                    const uint32_t kd = krow * 128 + ((ck ^ (krow & 7)) << 4);
                    uint32_t kh[4];
                    ldsm4(kh, sKh + kd);
                    mma16816(sacc[2*ntp],   qf[kc], kh);
                    mma16816(sacc[2*ntp+1], qf[kc], kh + 2);
                }
            }

            // ---- scale + causal mask ----
            const bool need_mask = (k0 + 63 > q0 + wq * 16);
#pragma unroll
            for (int nt = 0; nt < 8; nt++) {
#pragma unroll
                for (int j = 0; j < 4; j++) sacc[nt][j] *= 0.125f;
                if (need_mask) {
                    const int col = k0 + nt * 8 + 2 * t;
                    if (col     > qr0)     sacc[nt][0] = -1e30f;
                    if (col + 1 > qr0)     sacc[nt][1] = -1e30f;
                    if (col     > qr0 + 8) sacc[nt][2] = -1e30f;
                    if (col + 1 > qr0 + 8) sacc[nt][3] = -1e30f;
                }
            }

            // ---- online softmax ----
            float mx0 = -1e30f, mx1 = -1e30f;
#pragma unroll
            for (int nt = 0; nt < 8; nt++) {
                mx0 = fmaxf(mx0, fmaxf(sacc[nt][0], sacc[nt][1]));
                mx1 = fmaxf(mx1, fmaxf(sacc[nt][2], sacc[nt][3]));
            }
            mx0 = fmaxf(mx0, __shfl_xor_sync(0xffffffffu, mx0, 1));
            mx0 = fmaxf(mx0, __shfl_xor_sync(0xffffffffu, mx0, 2));
            mx1 = fmaxf(mx1, __shfl_xor_sync(0xffffffffu, mx1, 1));
            mx1 = fmaxf(mx1, __shfl_xor_sync(0xffffffffu, mx1, 2));
            const float mn0 = fmaxf(m0r, mx0);
            const float mn1 = fmaxf(m1r, mx1);
            const float al0 = __expf(m0r - mn0);
            const float al1 = __expf(m1r - mn1);
            m0r = mn0; m1r = mn1;

            float rs0 = 0.f, rs1 = 0.f;
#pragma unroll
            for (int nt = 0; nt < 8; nt++) {
                sacc[nt][0] = __expf(sacc[nt][0] - mn0);
                sacc[nt][1] = __expf(sacc[nt][1] - mn0);
                sacc[nt][2] = __expf(sacc[nt][2] - mn1);
                sacc[nt][3] = __expf(sacc[nt][3] - mn1);
                rs0 += sacc[nt][0] + sacc[nt][1];
                rs1 += sacc[nt][2] + sacc[nt][3];
            }
            rs0 += __shfl_xor_sync(0xffffffffu, rs0, 1);
            rs0 += __shfl_xor_sync(0xffffffffu, rs0, 2);
            rs1 += __shfl_xor_sync(0xffffffffu, rs1, 1);
            rs1 += __shfl_xor_sync(0xffffffffu, rs1, 2);
            l0r = l0r * al0 + rs0;
            l1r = l1r * al1 + rs1;
#pragma unroll
            for (int nt = 0; nt < 8; nt++) {
                oacc[nt][0] *= al0; oacc[nt][1] *= al0;
                oacc[nt][2] *= al1; oacc[nt][3] *= al1;
            }

            // ---- P fragments (split fp16, A-fragment layout) ----
            uint32_t ph[4][4], pl[4][4];
#pragma unroll
            for (int kc = 0; kc < 4; kc++) {
                split2(sacc[2*kc][0],   sacc[2*kc][1],   ph[kc][0], pl[kc][0]);
                split2(sacc[2*kc][2],   sacc[2*kc][3],   ph[kc][1], pl[kc][1]);
                split2(sacc[2*kc+1][0], sacc[2*kc+1][1], ph[kc][2], pl[kc][2]);
                split2(sacc[2*kc+1][2], sacc[2*kc+1][3], ph[kc][3], pl[kc][3]);
            }

            // ---- O += (Ph+Pl) Vh ----
#pragma unroll
            for (int ntp = 0; ntp < 4; ntp++) {
#pragma unroll
                for (int kc = 0; kc < 4; kc++) {
                    const int vrow = kc * 16 + ((g & 1) << 3) + l7;
                    const int vc   = 2 * ntp + (g >> 1);
                    const uint32_t vd = vrow * 128 + ((vc ^ (vrow & 7)) << 4);
                    uint32_t vh[4];
                    ldsm4t(vh, sVh + vd);
                    mma16816(oacc[2*ntp],   ph[kc], vh);
                    mma16816(oacc[2*ntp+1], ph[kc], vh + 2);
                    mma16816(oacc[2*ntp],   pl[kc], vh);
                    mma16816(oacc[2*ntp+1], pl[kc], vh + 2);
                }
            }
        }
    }

    // ---- epilogue: normalize, write single-fp16 y ----
    const float inv0 = 1.f / l0r;
    const float inv1 = 1.f / l1r;
    const size_t tok0 = (size_t)(b * Tq + q0 + wq * 16 + r);
    const size_t tok1 = tok0 + 8;
#pragma unroll
    for (int nt = 0; nt < 8; nt++) {
        const int col = h * Dq + nt * 8 + 2 * t;
        *(uint32_t*)(y + tok0 * Cq + col) = pack_h2(oacc[nt][0] * inv0, oacc[nt][1] * inv0);
        *(uint32_t*)(y + tok1 * Cq + col) = pack_h2(oacc[nt][2] * inv1, oacc[nt][3] * inv1);
    }
}

// ---------------------------------------------------------------------------
extern "C" void kernel_launch(void* const* d_in, const int* in_sizes, int n_in,
                              void* d_out, int out_size)
{
    const float* x      = (const float*)d_in[0];
    const float* w_attn = (const float*)d_in[1];
    const float* b_attn = (const float*)d_in[2];
    const float* w_proj = (const float*)d_in[3];
    const float* b_proj = (const float*)d_in[4];
    float* out = (float*)d_out;

    __half *qkv, *xh, *xl, *wah, *y, *wph;
    cudaGetSymbolAddress((void**)&qkv, g_qkv);
    cudaGetSymbolAddress((void**)&xh,  g_xh);
    cudaGetSymbolAddress((void**)&xl,  g_xl);
    cudaGetSymbolAddress((void**)&wah, g_wah);
    cudaGetSymbolAddress((void**)&y,   g_y);
    cudaGetSymbolAddress((void**)&wph, g_wph);

    cudaFuncSetAttribute(gemm_hmma<2, 1>,
                         cudaFuncAttributeMaxDynamicSharedMemorySize, GEMM_SMEM2);
    cudaFuncSetAttribute(gemm_hmma<1, 0>,
                         cudaFuncAttributeMaxDynamicSharedMemorySize, GEMM_SMEM1);
    cudaFuncSetAttribute(flash_hmma,
                         cudaFuncAttributeMaxDynamicSharedMemorySize, FLASH_SMEM);

    // x -> fp16 split; weights -> single fp16 RN
    {
        int n1 = NTOK * Cq;
        split_kernel<<<(n1 / 4 + 255) / 256, 256>>>(x, xh, xl, n1);
        int n2 = C3 * Cq;
        cvt_kernel<<<(n2 / 4 + 255) / 256, 256>>>(w_attn, wah, n2);
        int n3 = Cq * Cq;
        cvt_kernel<<<(n3 / 4 + 255) / 256, 256>>>(w_proj, wph, n3);
    }

    // 1) qkv = x @ w_attn^T + b_attn   (2-term A, single-fp16 output)
    {
        dim3 grid(C3 / BN, NTOK / BM);
        gemm_hmma<2, 1><<<grid, 256, GEMM_SMEM2>>>(xh, xl, wah, b_attn,
                                                   nullptr, qkv,
                                                   NTOK, C3, Cq);
    }
    // 2) tensorized flash attention -> single-fp16 y
    {
        dim3 grid(Tq / 128, Bq * Hq);
        flash_hmma<<<grid, 256, FLASH_SMEM>>>(qkv, y);
    }
    // 3) out = y @ w_proj^T + b_proj   (1-term, fp32 out)
    {
        dim3 grid(Cq / BN, NTOK / BM);
        gemm_hmma<1, 0><<<grid, 256, GEMM_SMEM1>>>(y, nullptr, wph, b_proj,
                                                   out, nullptr,
                                                   NTOK, Cq, Cq);
    }
}

// round 17
// speedup vs baseline: 1.4956x; 1.2868x over previous
#include <cuda_runtime.h>
#include <cuda_fp16.h>
#include <math.h>
#include <stdint.h>

// Problem constants
#define Bq   4
#define Tq   2048
#define Cq   1024
#define Hq   16
#define Dq   64
#define NTOK (Bq * Tq)        // 8192
#define C3   (3 * Cq)         // 3072

// ---------------------------------------------------------------------------
// Scratch (allocation-free rule: __device__ globals)
// ---------------------------------------------------------------------------
__device__ __half g_qkv[(size_t)NTOK * C3];   // single fp16 qkv
__device__ __half g_x[(size_t)NTOK * Cq];     // single fp16 x
__device__ __half g_wah[(size_t)C3 * Cq];     // w_attn single fp16
__device__ __half g_y[(size_t)NTOK * Cq];     // single fp16 y
__device__ __half g_wph[(size_t)Cq * Cq];     // w_proj single fp16

// ---------------------------------------------------------------------------
// Portable PTX helpers (sm_80+: cp.async, ldmatrix, mma.sync)
// ---------------------------------------------------------------------------
__device__ __forceinline__ uint32_t s2u(const void* p) {
    uint32_t a;
    asm("{ .reg .u64 t; cvta.to.shared.u64 t, %1; cvt.u32.u64 %0, t; }"
        : "=r"(a) : "l"(p));
    return a;
}
__device__ __forceinline__ void cp16(uint32_t s, const void* g) {
    asm volatile("cp.async.cg.shared.global [%0], [%1], 16;"
                 :: "r"(s), "l"(g) : "memory");
}
#define CP_COMMIT() asm volatile("cp.async.commit_group;" ::: "memory")
#define CP_WAIT0()  asm volatile("cp.async.wait_group 0;" ::: "memory")
#define CP_WAIT1()  asm volatile("cp.async.wait_group 1;" ::: "memory")

__device__ __forceinline__ void ldsm4(uint32_t* r, uint32_t a) {
    asm volatile("ldmatrix.sync.aligned.m8n8.x4.shared.b16 {%0,%1,%2,%3}, [%4];"
                 : "=r"(r[0]), "=r"(r[1]), "=r"(r[2]), "=r"(r[3]) : "r"(a));
}
__device__ __forceinline__ void ldsm4t(uint32_t* r, uint32_t a) {
    asm volatile("ldmatrix.sync.aligned.m8n8.x4.trans.shared.b16 {%0,%1,%2,%3}, [%4];"
                 : "=r"(r[0]), "=r"(r[1]), "=r"(r[2]), "=r"(r[3]) : "r"(a));
}
__device__ __forceinline__ void mma16816(float* c, const uint32_t* a,
                                         const uint32_t* b) {
    asm volatile("mma.sync.aligned.m16n8k16.row.col.f32.f16.f16.f32 "
                 "{%0,%1,%2,%3}, {%4,%5,%6,%7}, {%8,%9}, {%0,%1,%2,%3};"
                 : "+f"(c[0]), "+f"(c[1]), "+f"(c[2]), "+f"(c[3])
                 : "r"(a[0]), "r"(a[1]), "r"(a[2]), "r"(a[3]),
                   "r"(b[0]), "r"(b[1]));
}
__device__ __forceinline__ uint32_t pack_h2(float v0, float v1) {
    __half2 hh = __floats2half2_rn(v0, v1);
    return *(uint32_t*)&hh;
}

// fp32 -> single fp16 RN
__global__ void cvt_kernel(const float* __restrict__ src,
                           __half* __restrict__ dst, int n)
{
    int i = (blockIdx.x * blockDim.x + threadIdx.x) * 4;
    if (i >= n) return;
    float4 v = *(const float4*)(src + i);
    *(uint2*)(dst + i) = make_uint2(pack_h2(v.x, v.y), pack_h2(v.z, v.w));
}

// ---------------------------------------------------------------------------
// fp16 1-term HMMA GEMM: C = A @ B^T + bias (A, B single fp16; fp32 acc).
// OUTH=1: write single fp16 output.  OUTH=0: write fp32.
// 128x128x32 tile, 3-stage cp.async, 8 warps (4m x 2n), 2 CTAs/SM.
// ---------------------------------------------------------------------------
#define BM 128
#define BN 128
#define BK 32
#define MAT_B   (BM * 64)            // 8192 bytes per matrix tile
#define STAGE_B (2 * MAT_B)          // 16384 (A, B)
#define GEMM_SMEM (3 * STAGE_B)      // 49152

template<int OUTH>
__global__ __launch_bounds__(256, 2)
void gemm_hmma(const __half* __restrict__ A,
               const __half* __restrict__ B,
               const float* __restrict__ bias, float* __restrict__ C,
               __half* __restrict__ Ch,
               int M, int N, int K)
{
    extern __shared__ __align__(1024) char smem[];
    const uint32_t sbase = s2u(smem);
    const int tid  = threadIdx.x;
    const int wid  = tid >> 5;
    const int lane = tid & 31;
    const int m0 = blockIdx.y * BM;
    const int n0 = blockIdx.x * BN;
    const int NC = K / BK;

    const int wm = (wid >> 1) * 32;
    const int wn = (wid & 1) * 64;

    const int lrow = tid >> 1;
    const int lcs  = (tid & 1) * 2;
    const uint32_t so0 = lrow * 64 + ((lcs ^ (lrow & 3)) << 4);
    const uint32_t so1 = lrow * 64 + (((lcs + 1) ^ (lrow & 3)) << 4);

    const __half* gA = A + (size_t)(m0 + lrow) * K + lcs * 8;
    const __half* gB = B + (size_t)(n0 + lrow) * K + lcs * 8;

    auto load_stage = [&](int st, int c) {
        const uint32_t sb = sbase + st * STAGE_B;
        const int off = c * BK;
        cp16(sb + so0,           gA + off);
        cp16(sb + so1,           gA + off + 8);
        cp16(sb + MAT_B + so0,   gB + off);
        cp16(sb + MAT_B + so1,   gB + off + 8);
    };

    float acc[2][8][4];
#pragma unroll
    for (int i = 0; i < 2; i++)
#pragma unroll
        for (int j = 0; j < 8; j++)
#pragma unroll
            for (int k = 0; k < 4; k++) acc[i][j][k] = 0.f;

    const int g   = lane >> 3;
    const int l7  = lane & 7;
    const int arow = wm + (g & 1) * 8 + l7;
    const int achk = g >> 1;
    const int brow = wn + ((g & 2) << 2) + l7;
    const int bchk = g & 1;

    load_stage(0, 0); CP_COMMIT();
    load_stage(1, 1); CP_COMMIT();

    for (int c = 0; c < NC; c++) {
        const int st = c % 3;
        CP_WAIT1();
        __syncthreads();

        if (c + 2 < NC) load_stage((c + 2) % 3, c + 2);
        CP_COMMIT();

        const uint32_t sb = sbase + st * STAGE_B;
        const uint32_t sA = sb;
        const uint32_t sB = sb + MAT_B;

#pragma unroll
        for (int s = 0; s < 2; s++) {
            uint32_t ah[2][4];
#pragma unroll
            for (int mt = 0; mt < 2; mt++) {
                const int r = arow + mt * 16;
                const int ck = achk + 2 * s;
                const uint32_t ad = r * 64 + ((ck ^ (r & 3)) << 4);
                ldsm4(ah[mt], sA + ad);
            }
#pragma unroll
            for (int ng = 0; ng < 4; ng++) {
                const int r = brow + ng * 16;
                const int ck = bchk + 2 * s;
                const uint32_t bd = r * 64 + ((ck ^ (r & 3)) << 4);
                uint32_t bh[4];
                ldsm4(bh, sB + bd);
#pragma unroll
                for (int mt = 0; mt < 2; mt++) {
                    mma16816(acc[mt][2*ng],   ah[mt], bh);
                    mma16816(acc[mt][2*ng+1], ah[mt], bh + 2);
                }
            }
        }
        __syncthreads();
    }

    const int r = lane >> 2;
    const int t = lane & 3;
#pragma unroll
    for (int nt = 0; nt < 8; nt++) {
        const int col = n0 + wn + nt * 8 + t * 2;
        const float2 bv = *(const float2*)(bias + col);
#pragma unroll
        for (int mt = 0; mt < 2; mt++) {
            const int row0 = m0 + wm + mt * 16 + r;
            float v0 = acc[mt][nt][0] + bv.x, v1 = acc[mt][nt][1] + bv.y;
            float v2 = acc[mt][nt][2] + bv.x, v3 = acc[mt][nt][3] + bv.y;
            if (OUTH) {
                *(uint32_t*)(Ch + (size_t)row0 * N + col)       = pack_h2(v0, v1);
                *(uint32_t*)(Ch + (size_t)(row0 + 8) * N + col) = pack_h2(v2, v3);
            } else {
                *(float2*)(C + (size_t)row0 * N + col)       = make_float2(v0, v1);
                *(float2*)(C + (size_t)(row0 + 8) * N + col) = make_float2(v2, v3);
            }
        }
    }
}

// ---------------------------------------------------------------------------
// Tensorized flash attention (causal), fp32 softmax, ALL 1-term fp16:
// S = Q Kh^T, O += P Vh (P single fp16 after exp — post-exp quantization is
// a benign ~1.2e-4 relative perturbation; amplification lives pre-exp).
// Writes single-fp16 y. BQ=128, BKV=64, 8 warps, double-buffered K/V tiles.
// ---------------------------------------------------------------------------
#define FQ_B   16384                 // Q tile: 128 rows x 128 B
#define FKV_B  8192                  // one K or V tile: 64 rows x 128 B
#define FSTG_B (2 * FKV_B)           // Kh, Vh
#define FLASH_SMEM (FQ_B + 2 * FSTG_B)   // 49152

__global__ __launch_bounds__(256, 1)
void flash_hmma(const __half* __restrict__ qkv,
                __half* __restrict__ y)
{
    extern __shared__ __align__(1024) char smem[];
    const uint32_t sbase = s2u(smem);
    const uint32_t sQ = sbase;

    const int tid  = threadIdx.x;
    const int wq   = tid >> 5;            // warp: q rows wq*16..+15
    const int lane = tid & 31;
    const int qt   = gridDim.x - 1 - blockIdx.x;   // heavy CTAs first
    const int bh   = blockIdx.y;
    const int b    = bh >> 4;
    const int h    = bh & 15;
    const int q0   = qt * 128;
    const int jtmax = 2 * qt + 1;

    const int g  = lane >> 3;
    const int l7 = lane & 7;
    const int r  = lane >> 2;
    const int t  = lane & 3;

    // ---- load Q tile (single fp16) ----
    {
        const int row = tid >> 1;
        const int cb  = (tid & 1) * 4;
        const size_t gb = (size_t)(b * Tq + q0 + row) * C3 + h * Dq;
#pragma unroll
        for (int u = 0; u < 4; u++) {
            const int c = cb + u;
            const uint32_t off = row * 128 + ((c ^ (row & 7)) << 4);
            cp16(sQ + off, qkv + gb + c * 8);
        }
    }
    // ---- load K/V tile into stage s ----
    auto load_kv = [&](int jt, int s) {
        const uint32_t st = sbase + FQ_B + s * FSTG_B;
#pragma unroll
        for (int u = 0; u < 2; u++) {
            const int idx = tid * 2 + u;
            const int row = idx >> 3;
            const int c   = idx & 7;
            const uint32_t off = row * 128 + ((c ^ (row & 7)) << 4);
            const size_t gk = (size_t)(b * Tq + jt * 64 + row) * C3 + Cq + h * Dq + c * 8;
            const size_t gv = gk + Cq;
            cp16(st + off,           qkv + gk);
            cp16(st + FKV_B + off,   qkv + gv);
        }
    };
    load_kv(0, 0);
    CP_COMMIT();
    CP_WAIT0();
    __syncthreads();

    // ---- Q fragments (registers, 4 k-chunks x 4 regs) ----
    uint32_t qf[4][4];
    {
        const int arow = wq * 16 + (g & 1) * 8 + l7;
#pragma unroll
        for (int kc = 0; kc < 4; kc++) {
            const int ck = 2 * kc + (g >> 1);
            const uint32_t ad = arow * 128 + ((ck ^ (arow & 7)) << 4);
            ldsm4(qf[kc], sQ + ad);
        }
    }

    float oacc[8][4];
#pragma unroll
    for (int i = 0; i < 8; i++)
#pragma unroll
        for (int j = 0; j < 4; j++) oacc[i][j] = 0.f;
    float m0r = -1e30f, m1r = -1e30f, l0r = 0.f, l1r = 0.f;

    const int qr0 = q0 + wq * 16 + r;   // this lane's first q row
    const int kmax_w = q0 + wq * 16 + 15;

    for (int jt = 0; jt <= jtmax; jt++) {
        const int s = jt & 1;
        const int k0 = jt * 64;
        if (jt > 0) CP_WAIT0();
        __syncthreads();
        if (jt < jtmax) { load_kv(jt + 1, s ^ 1); CP_COMMIT(); }

        if (k0 <= kmax_w) {
            const uint32_t st  = sbase + FQ_B + s * FSTG_B;
            const uint32_t sKh = st;
            const uint32_t sVh = st + FKV_B;

            // ---- S = Q Kh^T (fp32 acc, 1-term) ----
            float sacc[8][4];
#pragma unroll
            for (int i = 0; i < 8; i++)
#pragma unroll
                for (int j = 0; j < 4; j++) sacc[i][j] = 0.f;

#pragma unroll
            for (int ntp = 0; ntp < 4; ntp++) {
                const int krow = ntp * 16 + ((g & 2) << 2) + l7;
#pragma unroll
                for (int kc = 0; kc < 4; kc++) {
                    const int ck = 2 * kc + (g & 1);
                    const uint32_t kd = krow * 128 + ((ck ^ (krow & 7)) << 4);
                    uint32_t kh[4];
                    ldsm4(kh, sKh + kd);
                    mma16816(sacc[2*ntp],   qf[kc], kh);
                    mma16816(sacc[2*ntp+1], qf[kc], kh + 2);
                }
            }

            // ---- scale + causal mask ----
            const bool need_mask = (k0 + 63 > q0 + wq * 16);
#pragma unroll
            for (int nt = 0; nt < 8; nt++) {
#pragma unroll
                for (int j = 0; j < 4; j++) sacc[nt][j] *= 0.125f;
                if (need_mask) {
                    const int col = k0 + nt * 8 + 2 * t;
                    if (col     > qr0)     sacc[nt][0] = -1e30f;
                    if (col + 1 > qr0)     sacc[nt][1] = -1e30f;
                    if (col     > qr0 + 8) sacc[nt][2] = -1e30f;
                    if (col + 1 > qr0 + 8) sacc[nt][3] = -1e30f;
                }
            }

            // ---- online softmax ----
            float mx0 = -1e30f, mx1 = -1e30f;
#pragma unroll
            for (int nt = 0; nt < 8; nt++) {
                mx0 = fmaxf(mx0, fmaxf(sacc[nt][0], sacc[nt][1]));
                mx1 = fmaxf(mx1, fmaxf(sacc[nt][2], sacc[nt][3]));
            }
            mx0 = fmaxf(mx0, __shfl_xor_sync(0xffffffffu, mx0, 1));
            mx0 = fmaxf(mx0, __shfl_xor_sync(0xffffffffu, mx0, 2));
            mx1 = fmaxf(mx1, __shfl_xor_sync(0xffffffffu, mx1, 1));
            mx1 = fmaxf(mx1, __shfl_xor_sync(0xffffffffu, mx1, 2));
            const float mn0 = fmaxf(m0r, mx0);
            const float mn1 = fmaxf(m1r, mx1);
            const float al0 = __expf(m0r - mn0);
            const float al1 = __expf(m1r - mn1);
            m0r = mn0; m1r = mn1;

            float rs0 = 0.f, rs1 = 0.f;
#pragma unroll
            for (int nt = 0; nt < 8; nt++) {
                sacc[nt][0] = __expf(sacc[nt][0] - mn0);
                sacc[nt][1] = __expf(sacc[nt][1] - mn0);
                sacc[nt][2] = __expf(sacc[nt][2] - mn1);
                sacc[nt][3] = __expf(sacc[nt][3] - mn1);
                rs0 += sacc[nt][0] + sacc[nt][1];
                rs1 += sacc[nt][2] + sacc[nt][3];
            }
            rs0 += __shfl_xor_sync(0xffffffffu, rs0, 1);
            rs0 += __shfl_xor_sync(0xffffffffu, rs0, 2);
            rs1 += __shfl_xor_sync(0xffffffffu, rs1, 1);
            rs1 += __shfl_xor_sync(0xffffffffu, rs1, 2);
            l0r = l0r * al0 + rs0;
            l1r = l1r * al1 + rs1;
#pragma unroll
            for (int nt = 0; nt < 8; nt++) {
                oacc[nt][0] *= al0; oacc[nt][1] *= al0;
                oacc[nt][2] *= al1; oacc[nt][3] *= al1;
            }

            // ---- P fragments (single fp16, A-fragment layout) ----
            uint32_t pf[4][4];
#pragma unroll
            for (int kc = 0; kc < 4; kc++) {
                pf[kc][0] = pack_h2(sacc[2*kc][0],   sacc[2*kc][1]);
                pf[kc][1] = pack_h2(sacc[2*kc][2],   sacc[2*kc][3]);
                pf[kc][2] = pack_h2(sacc[2*kc+1][0], sacc[2*kc+1][1]);
                pf[kc][3] = pack_h2(sacc[2*kc+1][2], sacc[2*kc+1][3]);
            }

            // ---- O += P Vh (1-term) ----
#pragma unroll
            for (int ntp = 0; ntp < 4; ntp++) {
#pragma unroll
                for (int kc = 0; kc < 4; kc++) {
                    const int vrow = kc * 16 + ((g & 1) << 3) + l7;
                    const int vc   = 2 * ntp + (g >> 1);
                    const uint32_t vd = vrow * 128 + ((vc ^ (vrow & 7)) << 4);
                    uint32_t vh[4];
                    ldsm4t(vh, sVh + vd);
                    mma16816(oacc[2*ntp],   pf[kc], vh);
                    mma16816(oacc[2*ntp+1], pf[kc], vh + 2);
                }
            }
        }
    }

    // ---- epilogue: normalize, write single-fp16 y ----
    const float inv0 = 1.f / l0r;
    const float inv1 = 1.f / l1r;
    const size_t tok0 = (size_t)(b * Tq + q0 + wq * 16 + r);
    const size_t tok1 = tok0 + 8;
#pragma unroll
    for (int nt = 0; nt < 8; nt++) {
        const int col = h * Dq + nt * 8 + 2 * t;
        *(uint32_t*)(y + tok0 * Cq + col) = pack_h2(oacc[nt][0] * inv0, oacc[nt][1] * inv0);
        *(uint32_t*)(y + tok1 * Cq + col) = pack_h2(oacc[nt][2] * inv1, oacc[nt][3] * inv1);
    }
}

// ---------------------------------------------------------------------------
extern "C" void kernel_launch(void* const* d_in, const int* in_sizes, int n_in,
                              void* d_out, int out_size)
{
    const float* x      = (const float*)d_in[0];
    const float* w_attn = (const float*)d_in[1];
    const float* b_attn = (const float*)d_in[2];
    const float* w_proj = (const float*)d_in[3];
    const float* b_proj = (const float*)d_in[4];
    float* out = (float*)d_out;

    __half *qkv, *xs, *wah, *y, *wph;
    cudaGetSymbolAddress((void**)&qkv, g_qkv);
    cudaGetSymbolAddress((void**)&xs,  g_x);
    cudaGetSymbolAddress((void**)&wah, g_wah);
    cudaGetSymbolAddress((void**)&y,   g_y);
    cudaGetSymbolAddress((void**)&wph, g_wph);

    cudaFuncSetAttribute(gemm_hmma<1>,
                         cudaFuncAttributeMaxDynamicSharedMemorySize, GEMM_SMEM);
    cudaFuncSetAttribute(gemm_hmma<0>,
                         cudaFuncAttributeMaxDynamicSharedMemorySize, GEMM_SMEM);
    cudaFuncSetAttribute(flash_hmma,
                         cudaFuncAttributeMaxDynamicSharedMemorySize, FLASH_SMEM);

    // convert all inputs to single fp16
    {
        int n1 = NTOK * Cq;
        cvt_kernel<<<(n1 / 4 + 255) / 256, 256>>>(x, xs, n1);
        int n2 = C3 * Cq;
        cvt_kernel<<<(n2 / 4 + 255) / 256, 256>>>(w_attn, wah, n2);
        int n3 = Cq * Cq;
        cvt_kernel<<<(n3 / 4 + 255) / 256, 256>>>(w_proj, wph, n3);
    }

    // 1) qkv = x @ w_attn^T + b_attn   (1-term, single-fp16 output)
    {
        dim3 grid(C3 / BN, NTOK / BM);
        gemm_hmma<1><<<grid, 256, GEMM_SMEM>>>(xs, wah, b_attn,
                                               nullptr, qkv,
                                               NTOK, C3, Cq);
    }
    // 2) tensorized flash attention (all 1-term) -> single-fp16 y
    {
        dim3 grid(Tq / 128, Bq * Hq);
        flash_hmma<<<grid, 256, FLASH_SMEM>>>(qkv, y);
    }
    // 3) out = y @ w_proj^T + b_proj   (1-term, fp32 out)
    {
        dim3 grid(Cq / BN, NTOK / BM);
        gemm_hmma<0><<<grid, 256, GEMM_SMEM>>>(y, wph, b_proj,
                                               out, nullptr,
                                               NTOK, Cq, Cq);
    }
}